// round 1
// baseline (speedup 1.0000x reference)
#include <cuda_runtime.h>
#include <cstdint>

// ---------------------------------------------------------------------------
// Problem constants
// ---------------------------------------------------------------------------
#define N_NODES 512
#define N_CLS   151
#define E_EDGES 50000
#define E_CLS   51
#define D_DIM   1024
#define NMS_TH  0.3f

// Output layout (concatenated tuple, float32):
//   raw_edge_class : [50000, 51]   @ 0
//   h_edge_emb     : [50000, 1024] @ 2,550,000   (all zeros)
//   raw_node_class : [512, 151]    @ 53,750,000
//   h_node_emb     : [512, 1024]   @ 53,827,312
static constexpr long long OFF_REC = 0LL;
static constexpr long long OFF_HEE = 2550000LL;
static constexpr long long OFF_RNC = 53750000LL;
static constexpr long long OFF_HNE = 53827312LL;

#define NMS_BLOCKS  150
#define GEMM_BLOCKS 391          // ceil(50000 / 128)
#define FILL_BLOCKS 160

// ---------------------------------------------------------------------------
// Device scratch (no cudaMalloc allowed)
// ---------------------------------------------------------------------------
__device__ float g_att [N_NODES * N_CLS];   // softmax(raw_node_class)
__device__ float g_mask[N_NODES * N_CLS];   // NMS keep mask (col 0 forced 0)
__device__ float g_schT[N_CLS * D_DIM];     // nodes_schema transposed [151][1024]

// ---------------------------------------------------------------------------
// K1: raw_node_class = node_emb @ nodes_schema ; softmax -> g_att
//     128 blocks x 4 nodes, 192 threads (threads c<151 compute one class col)
// ---------------------------------------------------------------------------
__global__ __launch_bounds__(192) void k1_node(
    const float* __restrict__ node_emb,
    const float* __restrict__ nsch,
    float* __restrict__ out)
{
    __shared__ float Arow[4][D_DIM];
    __shared__ float raw [4][N_CLS];
    __shared__ float mxs[4], sms[4];

    const int n0  = blockIdx.x * 4;
    const int tid = threadIdx.x;

    for (int t = tid; t < 4 * D_DIM; t += 192) {
        int n = t >> 10, d = t & 1023;
        Arow[n][d] = node_emb[(long long)(n0 + n) * D_DIM + d];
    }
    __syncthreads();

    const int c = tid;
    if (c < N_CLS) {
        float a0 = 0.f, a1 = 0.f, a2 = 0.f, a3 = 0.f;
        const float* sp = nsch + c;
        for (int d = 0; d < D_DIM; ++d) {
            float b = sp[(long long)d * N_CLS];   // coalesced across c
            a0 += Arow[0][d] * b;
            a1 += Arow[1][d] * b;
            a2 += Arow[2][d] * b;
            a3 += Arow[3][d] * b;
        }
        raw[0][c] = a0; raw[1][c] = a1; raw[2][c] = a2; raw[3][c] = a3;
    }
    __syncthreads();

    if (tid < 4) {
        float mx = -1e30f;
        for (int i = 0; i < N_CLS; ++i) mx = fmaxf(mx, raw[tid][i]);
        float s = 0.f;
        for (int i = 0; i < N_CLS; ++i) s += expf(raw[tid][i] - mx);
        mxs[tid] = mx; sms[tid] = s;
    }
    __syncthreads();

    if (c < N_CLS) {
        #pragma unroll
        for (int n = 0; n < 4; ++n) {
            float v   = raw[n][c];
            float att = expf(v - mxs[n]) / sms[n];
            long long gi = (long long)(n0 + n) * N_CLS + c;
            g_att[gi]          = att;
            out[OFF_RNC + gi]  = v;
            if (c == 0) g_mask[gi] = 0.f;   // class 0 excluded from NMS mask
        }
    }
}

// ---------------------------------------------------------------------------
// K2 shared-memory union: GEMM tile vs NMS workspace
// ---------------------------------------------------------------------------
struct NmsSmem {
    unsigned long long keys[512];                         // 4 KB
    float bx1[512], by1[512], bx2[512], by2[512], ar[512];// 10 KB
    unsigned supp[512];                                   // 2 KB
};
struct GemmSmem {
    float As[32][129];   // [k][m], padded vs bank conflicts  (16.5 KB)
    float Bs[32][64];    // [k][c], cols 51..63 zero           (8 KB)
};
union K2Smem { NmsSmem nms; GemmSmem g; };

// ---------------------------------------------------------------------------
// Edge GEMM block: C[128 rows x 51] tile. 256 thr = 32 m-groups x 8 n-groups,
// each thread 4 rows x 8 cols (4 f32x2 pairs). fma.rn.f32x2 = 2x FFMA tput.
// ---------------------------------------------------------------------------
__device__ __forceinline__ void gemm_block(
    GemmSmem& sm, int gb,
    const float* __restrict__ A, const float* __restrict__ B,
    float* __restrict__ C)
{
    const int tid   = threadIdx.x;
    const int n_idx = tid & 7;
    const int m4    = (tid >> 3) * 4;
    const long long row0 = (long long)gb * 128;

    unsigned long long acc[4][4];
    #pragma unroll
    for (int r = 0; r < 4; ++r)
        #pragma unroll
        for (int p = 0; p < 4; ++p) acc[r][p] = 0ULL;

    const int kl = tid & 31;   // k lane within chunk (coalesced A loads)
    const int ml = tid >> 5;   // starting m for this thread's A loads

    for (int kc = 0; kc < D_DIM; kc += 32) {
        #pragma unroll
        for (int mm = ml; mm < 128; mm += 8) {
            long long r = row0 + mm;
            sm.As[kl][mm] = (r < E_EDGES) ? A[r * D_DIM + kc + kl] : 0.f;
        }
        #pragma unroll
        for (int t = tid; t < 32 * 64; t += 256) {
            int kk = t >> 6, cc = t & 63;
            sm.Bs[kk][cc] = (cc < E_CLS) ? B[(long long)(kc + kk) * E_CLS + cc] : 0.f;
        }
        __syncthreads();

        #pragma unroll 4
        for (int k = 0; k < 32; ++k) {
            unsigned long long bv[4];
            #pragma unroll
            for (int p = 0; p < 4; ++p)
                bv[p] = *reinterpret_cast<const unsigned long long*>(
                            &sm.Bs[k][(n_idx * 4 + p) * 2]);
            #pragma unroll
            for (int r = 0; r < 4; ++r) {
                float a = sm.As[k][m4 + r];
                unsigned long long av;
                asm("mov.b64 %0, {%1, %1};" : "=l"(av) : "f"(a));
                #pragma unroll
                for (int p = 0; p < 4; ++p)
                    asm("fma.rn.f32x2 %0, %1, %2, %0;"
                        : "+l"(acc[r][p]) : "l"(av), "l"(bv[p]));
            }
        }
        __syncthreads();
    }

    #pragma unroll
    for (int r = 0; r < 4; ++r) {
        long long row = row0 + m4 + r;
        if (row >= E_EDGES) continue;
        #pragma unroll
        for (int p = 0; p < 4; ++p) {
            int c0 = (n_idx * 4 + p) * 2;
            unsigned lo, hi;
            asm("mov.b64 {%0, %1}, %2;" : "=r"(lo), "=r"(hi) : "l"(acc[r][p]));
            if (c0     < E_CLS) C[row * E_CLS + c0]     = __uint_as_float(lo);
            if (c0 + 1 < E_CLS) C[row * E_CLS + c0 + 1] = __uint_as_float(hi);
        }
    }
}

// ---------------------------------------------------------------------------
// NMS block: one class, 512 boxes, 256 threads.
// Stable descending sort via packed u64 key (score_bits || ~node). Softmax
// scores are strictly positive so raw fp32 bits order == float order.
// Greedy loop computes IoU on the fly; barrier only on kept boxes.
// ---------------------------------------------------------------------------
__device__ void nms_block(NmsSmem& sm, int cls, const float* __restrict__ boxes)
{
    const int tid = threadIdx.x;

    for (int t = tid; t < 512; t += 256) {
        float s = g_att[(long long)t * N_CLS + cls];
        sm.keys[t] = ((unsigned long long)__float_as_uint(s) << 32)
                   | (unsigned)(0xFFFFFFFFu - (unsigned)t);
    }
    __syncthreads();

    // bitonic sort, descending
    for (unsigned k = 2; k <= 512; k <<= 1) {
        for (unsigned j = k >> 1; j > 0; j >>= 1) {
            for (unsigned t = tid; t < 512; t += 256) {
                unsigned l = t ^ j;
                if (l > t) {
                    unsigned long long a = sm.keys[t], b = sm.keys[l];
                    bool desc = ((t & k) == 0);
                    if (desc ? (a < b) : (a > b)) { sm.keys[t] = b; sm.keys[l] = a; }
                }
            }
            __syncthreads();
        }
    }

    for (int s = tid; s < 512; s += 256) {
        unsigned node = 0xFFFFFFFFu - (unsigned)(sm.keys[s] & 0xFFFFFFFFull);
        const float* bp = boxes + ((long long)node * N_CLS + cls) * 4;
        float x1 = bp[0], y1 = bp[1], x2 = bp[2], y2 = bp[3];
        sm.bx1[s] = x1; sm.by1[s] = y1; sm.bx2[s] = x2; sm.by2[s] = y2;
        sm.ar[s]  = (x2 - x1) * (y2 - y1);
        sm.supp[s] = 0u;
    }
    __syncthreads();

    volatile unsigned* supp = sm.supp;
    for (int i = 0; i < 512; ++i) {
        if (supp[i]) continue;               // uniform branch, no barrier
        float xi1 = sm.bx1[i], yi1 = sm.by1[i];
        float xi2 = sm.bx2[i], yi2 = sm.by2[i], ai = sm.ar[i];
        #pragma unroll
        for (int h = 0; h < 2; ++h) {
            int j = tid + h * 256;
            if (j > i) {
                float ix1 = fmaxf(xi1, sm.bx1[j]);
                float iy1 = fmaxf(yi1, sm.by1[j]);
                float ix2 = fminf(xi2, sm.bx2[j]);
                float iy2 = fminf(yi2, sm.by2[j]);
                float iw  = fmaxf(ix2 - ix1, 0.f);
                float ih  = fmaxf(iy2 - iy1, 0.f);
                float inter = iw * ih;
                float iou = inter / (ai + sm.ar[j] - inter);
                if (iou > NMS_TH) supp[j] = 1u;
            }
        }
        __syncthreads();
    }

    for (int s = tid; s < 512; s += 256) {
        unsigned node = 0xFFFFFFFFu - (unsigned)(sm.keys[s] & 0xFFFFFFFFull);
        g_mask[(long long)node * N_CLS + cls] = sm.supp[s] ? 0.f : 1.f;
    }
}

// ---------------------------------------------------------------------------
// Fill block: zero h_edge_emb (float4 streaming stores); first 8 blocks also
// transpose nodes_schema -> g_schT for coalesced reads in K3.
// ---------------------------------------------------------------------------
__device__ void fill_block(int fb, const float* __restrict__ nsch,
                           float* __restrict__ out)
{
    const int tid = threadIdx.x;
    if (fb < 8) {
        for (int e = fb * 256 + tid; e < N_CLS * D_DIM; e += 8 * 256) {
            int c = e >> 10, d = e & 1023;
            g_schT[e] = nsch[(long long)d * N_CLS + c];
        }
    }
    float4* z = reinterpret_cast<float4*>(out + OFF_HEE);
    const long long n4 = (long long)E_EDGES * D_DIM / 4;   // 12.8M
    const float4 zero = make_float4(0.f, 0.f, 0.f, 0.f);
    for (long long i = (long long)fb * 256 + tid; i < n4;
         i += (long long)FILL_BLOCKS * 256)
        z[i] = zero;
}

// ---------------------------------------------------------------------------
// K2: fused grid — [0,150) NMS | [150,541) edge GEMM | [541,701) fill/transpose
// ---------------------------------------------------------------------------
__global__ __launch_bounds__(256) void k2_main(
    const float* __restrict__ edge_emb,
    const float* __restrict__ esch,
    const float* __restrict__ boxes,
    const float* __restrict__ nsch,
    float* __restrict__ out)
{
    __shared__ K2Smem sm;
    const int b = blockIdx.x;
    if (b < NMS_BLOCKS) {
        nms_block(sm.nms, b + 1, boxes);
    } else if (b < NMS_BLOCKS + GEMM_BLOCKS) {
        gemm_block(sm.g, b - NMS_BLOCKS, edge_emb, esch, out + OFF_REC);
    } else {
        fill_block(b - NMS_BLOCKS - GEMM_BLOCKS, nsch, out);
    }
}

// ---------------------------------------------------------------------------
// K3: h_node_emb = (att * mask) @ nodes_schema.T   [512,151]x[151,1024]
//     128 blocks x 4 nodes, 256 threads x 4 d-cols
// ---------------------------------------------------------------------------
__global__ __launch_bounds__(256) void k3_hnode(float* __restrict__ out)
{
    __shared__ float am[4][N_CLS];
    const int n0  = blockIdx.x * 4;
    const int tid = threadIdx.x;

    for (int t = tid; t < 4 * N_CLS; t += 256) {
        int n = t / N_CLS, c = t - n * N_CLS;
        long long gi = (long long)(n0 + n) * N_CLS + c;
        am[n][c] = g_att[gi] * g_mask[gi];
    }
    __syncthreads();

    float acc[4][4] = {};
    for (int c = 0; c < N_CLS; ++c) {
        float s0 = g_schT[c * D_DIM + tid];
        float s1 = g_schT[c * D_DIM + tid + 256];
        float s2 = g_schT[c * D_DIM + tid + 512];
        float s3 = g_schT[c * D_DIM + tid + 768];
        #pragma unroll
        for (int n = 0; n < 4; ++n) {
            float a = am[n][c];
            acc[n][0] += a * s0; acc[n][1] += a * s1;
            acc[n][2] += a * s2; acc[n][3] += a * s3;
        }
    }
    #pragma unroll
    for (int n = 0; n < 4; ++n)
        #pragma unroll
        for (int i = 0; i < 4; ++i)
            out[OFF_HNE + (long long)(n0 + n) * D_DIM + tid + i * 256] = acc[n][i];
}

// ---------------------------------------------------------------------------
// Entry point — inputs identified by element count (robust to ordering):
//   node_emb 524288 | edge_emb 51200000 | boxes 309248 |
//   nodes_schema 154624 | edges_schema 52224
// ---------------------------------------------------------------------------
extern "C" void kernel_launch(void* const* d_in, const int* in_sizes, int n_in,
                              void* d_out, int out_size)
{
    const float *node_emb = nullptr, *edge_emb = nullptr, *boxes = nullptr,
                *nsch = nullptr, *esch = nullptr;
    for (int i = 0; i < n_in; ++i) {
        switch (in_sizes[i]) {
            case 524288:   node_emb = (const float*)d_in[i]; break;
            case 51200000: edge_emb = (const float*)d_in[i]; break;
            case 309248:   boxes    = (const float*)d_in[i]; break;
            case 154624:   nsch     = (const float*)d_in[i]; break;
            case 52224:    esch     = (const float*)d_in[i]; break;
            default: break;
        }
    }
    float* out = (float*)d_out;

    k1_node<<<128, 192>>>(node_emb, nsch, out);
    k2_main<<<NMS_BLOCKS + GEMM_BLOCKS + FILL_BLOCKS, 256>>>(
        edge_emb, esch, boxes, nsch, out);
    k3_hnode<<<128, 256>>>(out);
}

// round 6
// speedup vs baseline: 1.5409x; 1.5409x over previous
#include <cuda_runtime.h>
#include <cuda_bf16.h>
#include <cstdint>

// ---------------------------------------------------------------------------
// Problem constants
// ---------------------------------------------------------------------------
#define N_NODES 512
#define N_CLS   151
#define E_EDGES 50000
#define E_CLS   51
#define D_DIM   1024
#define NMS_TH  0.3f

// Output layout (concatenated tuple, float32)
static constexpr long long OFF_REC = 0LL;           // raw_edge_class [50000,51]
static constexpr long long OFF_HEE = 2550000LL;     // h_edge_emb     [50000,1024] zeros
static constexpr long long OFF_RNC = 53750000LL;    // raw_node_class [512,151]
static constexpr long long OFF_HNE = 53827312LL;    // h_node_emb     [512,1024]

#define NMS_BLOCKS  150
#define GEMM_BLOCKS 391          // ceil(50000 / 128)
#define FILL_BLOCKS 160

#define A_STRIDE 40              // bf16 elems per SMEM row (32 used + 8 pad)

// ---------------------------------------------------------------------------
// Device scratch (no cudaMalloc allowed)
// ---------------------------------------------------------------------------
__device__ float g_att [N_NODES * N_CLS];
__device__ float g_mask[N_NODES * N_CLS];
__device__ float g_schT[N_CLS * D_DIM];              // nodes_schema^T [151][1024]
__device__ __nv_bfloat16 g_Bhi[64 * D_DIM];          // edges_schema^T hi [64][1024]
__device__ __nv_bfloat16 g_Blo[64 * D_DIM];          // edges_schema^T lo

// ---------------------------------------------------------------------------
// Helpers (plain sm_100-compatible: ldmatrix / mma.sync bf16 / cvt.bf16x2)
// ---------------------------------------------------------------------------
__device__ __forceinline__ uint32_t smem_u32(const void* p) {
    uint32_t a;
    asm("{ .reg .u64 t; cvta.to.shared.u64 t, %1; cvt.u32.u64 %0, t; }"
        : "=r"(a) : "l"(p));
    return a;
}

// pack {hi_elem, lo_elem} -> bf16x2 (hi source goes to bits[31:16])
__device__ __forceinline__ uint32_t cvt_bf16x2(float hi, float lo) {
    uint32_t r;
    asm("cvt.rn.bf16x2.f32 %0, %1, %2;" : "=r"(r) : "f"(hi), "f"(lo));
    return r;
}

__device__ __forceinline__ void ldsm_x4(uint32_t* r, uint32_t addr) {
    asm volatile("ldmatrix.sync.aligned.m8n8.x4.shared.b16 {%0,%1,%2,%3}, [%4];"
                 : "=r"(r[0]), "=r"(r[1]), "=r"(r[2]), "=r"(r[3]) : "r"(addr));
}
__device__ __forceinline__ void ldsm_x2(uint32_t* r, uint32_t addr) {
    asm volatile("ldmatrix.sync.aligned.m8n8.x2.shared.b16 {%0,%1}, [%2];"
                 : "=r"(r[0]), "=r"(r[1]) : "r"(addr));
}

__device__ __forceinline__ void mma_bf16(float* c, const uint32_t* a,
                                         const uint32_t* b) {
    asm volatile(
        "mma.sync.aligned.m16n8k16.row.col.f32.bf16.bf16.f32 "
        "{%0,%1,%2,%3}, {%4,%5,%6,%7}, {%8,%9}, {%0,%1,%2,%3};"
        : "+f"(c[0]), "+f"(c[1]), "+f"(c[2]), "+f"(c[3])
        : "r"(a[0]), "r"(a[1]), "r"(a[2]), "r"(a[3]), "r"(b[0]), "r"(b[1]));
}

// ---------------------------------------------------------------------------
// K0: prep — transpose nodes_schema -> g_schT; transpose+split edges_schema
//     -> g_Bhi/g_Blo (rows 51..63 zero).  Grid: 151 + 64 = 215 blocks.
// ---------------------------------------------------------------------------
__global__ __launch_bounds__(256) void k0_prep(
    const float* __restrict__ nsch, const float* __restrict__ esch)
{
    const int b = blockIdx.x, tid = threadIdx.x;
    if (b < N_CLS) {
        for (int d = tid; d < D_DIM; d += 256)
            g_schT[b * D_DIM + d] = nsch[(long long)d * N_CLS + b];
    } else {
        const int n = b - N_CLS;   // 0..63
        for (int k = tid; k < D_DIM; k += 256) {
            float v = (n < E_CLS) ? esch[(long long)k * E_CLS + n] : 0.f;
            __nv_bfloat16 h = __float2bfloat16(v);
            g_Bhi[n * D_DIM + k] = h;
            g_Blo[n * D_DIM + k] = __float2bfloat16(v - __bfloat162float(h));
        }
    }
}

// ---------------------------------------------------------------------------
// K1: raw_node_class + softmax -> g_att.  128 blocks x 4 nodes, 256 threads.
//     K split across 32 lanes + shuffle reduce (MLP ~32 per item).
// ---------------------------------------------------------------------------
__global__ __launch_bounds__(256) void k1_node(
    const float* __restrict__ node_emb, float* __restrict__ out)
{
    __shared__ float Arow[4][D_DIM];
    __shared__ float raw[4 * N_CLS];
    __shared__ float mxs[4], sms[4];

    const int n0 = blockIdx.x * 4;
    const int tid = threadIdx.x;
    const int wid = tid >> 5, lane = tid & 31;

    const float4* src = (const float4*)(node_emb + (long long)n0 * D_DIM);
    float4* dst = (float4*)&Arow[0][0];
    for (int i = tid; i < 4 * D_DIM / 4; i += 256) dst[i] = src[i];
    __syncthreads();

    for (int item = wid; item < 4 * N_CLS; item += 8) {
        const int n = item / N_CLS, c = item - n * N_CLS;
        const float* sp = g_schT + c * D_DIM + lane;
        const float* ap = &Arow[n][lane];
        float s = 0.f;
        #pragma unroll
        for (int j = 0; j < 32; ++j) s += sp[32 * j] * ap[32 * j];
        #pragma unroll
        for (int o = 16; o; o >>= 1) s += __shfl_xor_sync(0xFFFFFFFFu, s, o);
        if (lane == 0) raw[item] = s;
    }
    __syncthreads();

    if (tid < 4) {
        float mx = -1e30f;
        for (int i = 0; i < N_CLS; ++i) mx = fmaxf(mx, raw[tid * N_CLS + i]);
        float s = 0.f;
        for (int i = 0; i < N_CLS; ++i) s += expf(raw[tid * N_CLS + i] - mx);
        mxs[tid] = mx; sms[tid] = s;
    }
    __syncthreads();

    if (tid < N_CLS) {
        const int c = tid;
        #pragma unroll
        for (int n = 0; n < 4; ++n) {
            float v = raw[n * N_CLS + c];
            float att = expf(v - mxs[n]) / sms[n];
            long long gi = (long long)(n0 + n) * N_CLS + c;
            g_att[gi] = att;
            out[OFF_RNC + gi] = v;
            if (c == 0) g_mask[gi] = 0.f;
        }
    }
}

// ---------------------------------------------------------------------------
// K2 smem union
// ---------------------------------------------------------------------------
struct NmsSmem {
    unsigned long long keys[512];
    float bx1[512], by1[512], bx2[512], by2[512], ar[512];
    unsigned supp[512];
};
struct GemmSmem {
    __nv_bfloat16 Ahi[128 * A_STRIDE];   // 10240 B
    __nv_bfloat16 Alo[128 * A_STRIDE];   // 10240 B
    __nv_bfloat16 Bhi[64 * A_STRIDE];    //  5120 B
    __nv_bfloat16 Blo[64 * A_STRIDE];    //  5120 B
};
union __align__(16) K2Smem { NmsSmem nms; GemmSmem g; };   // 30720 B

// ---------------------------------------------------------------------------
// HMMA split-precision edge GEMM: C[128 x 51] tile, K=1024, chunks of 32.
// fp32 = bf16_hi + bf16_lo; D = AhBh + AhBl + AlBh (fp32 accum).
// 8 warps x (16 rows x 64 cols); mma.sync m16n8k16 via ldmatrix fragments.
// ---------------------------------------------------------------------------
__device__ void gemm_block(GemmSmem& sm, int gb,
                           const float* __restrict__ A, float* __restrict__ C)
{
    const int tid  = threadIdx.x;
    const int lane = tid & 31, w = tid >> 5;
    const long long row0 = (long long)gb * 128;

    float acc[8][4];
    #pragma unroll
    for (int nb = 0; nb < 8; ++nb)
        #pragma unroll
        for (int i = 0; i < 4; ++i) acc[nb][i] = 0.f;

    const uint32_t ahi_a = smem_u32(sm.Ahi), alo_a = smem_u32(sm.Alo);
    const uint32_t bhi_a = smem_u32(sm.Bhi), blo_a = smem_u32(sm.Blo);

    // A gmem load assignment: thread -> (row, k-half)
    const int lrow  = tid & 127;
    const int lhalf = tid >> 7;                // 0/1 -> k offset 0/16
    const long long grow = row0 + lrow;
    const bool gvalid = grow < E_EDGES;
    const float4* agp = (const float4*)(A + grow * D_DIM + lhalf * 16);

    // B gmem load assignment: thread -> (n, quarter)
    const int bn = tid >> 2, bq = tid & 3;

    // ldmatrix fragment base offsets (bytes)
    const uint32_t a_off = (uint32_t)((w * 16 + (lane & 15)) * A_STRIDE
                                      + ((lane & 16) >> 1)) * 2;
    const uint32_t b_off = (uint32_t)((lane & 7) * A_STRIDE + (lane & 8)) * 2;

    for (int kc = 0; kc < D_DIM; kc += 32) {
        // issue gmem loads first (in flight across the barrier below)
        float4 f[4];
        #pragma unroll
        for (int i = 0; i < 4; ++i)
            f[i] = gvalid ? agp[(kc >> 2) + i] : make_float4(0.f, 0.f, 0.f, 0.f);
        uint4 bhv = *(const uint4*)(g_Bhi + bn * D_DIM + kc + bq * 8);
        uint4 blv = *(const uint4*)(g_Blo + bn * D_DIM + kc + bq * 8);

        __syncthreads();   // prior chunk's ldmatrix reads complete

        // convert A -> hi/lo bf16, store to SMEM
        #pragma unroll
        for (int i = 0; i < 4; ++i) {
            uint32_t h0 = cvt_bf16x2(f[i].y, f[i].x);
            uint32_t h1 = cvt_bf16x2(f[i].w, f[i].z);
            float r0 = f[i].x - __uint_as_float(h0 << 16);
            float r1 = f[i].y - __uint_as_float(h0 & 0xFFFF0000u);
            float r2 = f[i].z - __uint_as_float(h1 << 16);
            float r3 = f[i].w - __uint_as_float(h1 & 0xFFFF0000u);
            uint32_t l0 = cvt_bf16x2(r1, r0);
            uint32_t l1 = cvt_bf16x2(r3, r2);
            const int eoff = lrow * A_STRIDE + lhalf * 16 + i * 4;
            *(uint2*)((char*)sm.Ahi + eoff * 2) = make_uint2(h0, h1);
            *(uint2*)((char*)sm.Alo + eoff * 2) = make_uint2(l0, l1);
        }
        {
            const int eoff = bn * A_STRIDE + bq * 8;
            *(uint4*)((char*)sm.Bhi + eoff * 2) = bhv;
            *(uint4*)((char*)sm.Blo + eoff * 2) = blv;
        }
        __syncthreads();

        // compute: 2 k-steps of 16
        #pragma unroll
        for (int ks = 0; ks < 2; ++ks) {
            uint32_t ah[4], al[4];
            ldsm_x4(ah, ahi_a + a_off + ks * 32);
            ldsm_x4(al, alo_a + a_off + ks * 32);
            #pragma unroll
            for (int nb = 0; nb < 8; ++nb) {
                uint32_t bh[2], bl[2];
                ldsm_x2(bh, bhi_a + b_off + nb * (8 * A_STRIDE * 2) + ks * 32);
                ldsm_x2(bl, blo_a + b_off + nb * (8 * A_STRIDE * 2) + ks * 32);
                mma_bf16(acc[nb], ah, bh);
                mma_bf16(acc[nb], ah, bl);
                mma_bf16(acc[nb], al, bh);
            }
        }
    }

    // epilogue: lane holds D rows (w*16 + lane/4 + {0,8}), cols nb*8+(lane&3)*2
    const long long rbase = row0 + w * 16 + (lane >> 2);
    const int cb = (lane & 3) * 2;
    #pragma unroll
    for (int nb = 0; nb < 8; ++nb) {
        const int c0 = nb * 8 + cb;
        if (c0 >= E_CLS && c0 + 1 >= E_CLS) continue;
        #pragma unroll
        for (int h = 0; h < 2; ++h) {
            const long long row = rbase + 8 * h;
            if (row < E_EDGES) {
                if (c0 < E_CLS)     C[row * E_CLS + c0]     = acc[nb][2 * h];
                if (c0 + 1 < E_CLS) C[row * E_CLS + c0 + 1] = acc[nb][2 * h + 1];
            }
        }
    }
}

// ---------------------------------------------------------------------------
// NMS block (unchanged from R1-passing kernel)
// ---------------------------------------------------------------------------
__device__ void nms_block(NmsSmem& sm, int cls, const float* __restrict__ boxes)
{
    const int tid = threadIdx.x;

    for (int t = tid; t < 512; t += 256) {
        float s = g_att[(long long)t * N_CLS + cls];
        sm.keys[t] = ((unsigned long long)__float_as_uint(s) << 32)
                   | (unsigned)(0xFFFFFFFFu - (unsigned)t);
    }
    __syncthreads();

    for (unsigned k = 2; k <= 512; k <<= 1) {
        for (unsigned j = k >> 1; j > 0; j >>= 1) {
            for (unsigned t = tid; t < 512; t += 256) {
                unsigned l = t ^ j;
                if (l > t) {
                    unsigned long long a = sm.keys[t], b = sm.keys[l];
                    bool desc = ((t & k) == 0);
                    if (desc ? (a < b) : (a > b)) { sm.keys[t] = b; sm.keys[l] = a; }
                }
            }
            __syncthreads();
        }
    }

    for (int s = tid; s < 512; s += 256) {
        unsigned node = 0xFFFFFFFFu - (unsigned)(sm.keys[s] & 0xFFFFFFFFull);
        const float* bp = boxes + ((long long)node * N_CLS + cls) * 4;
        float x1 = bp[0], y1 = bp[1], x2 = bp[2], y2 = bp[3];
        sm.bx1[s] = x1; sm.by1[s] = y1; sm.bx2[s] = x2; sm.by2[s] = y2;
        sm.ar[s]  = (x2 - x1) * (y2 - y1);
        sm.supp[s] = 0u;
    }
    __syncthreads();

    volatile unsigned* supp = sm.supp;
    for (int i = 0; i < 512; ++i) {
        if (supp[i]) continue;
        float xi1 = sm.bx1[i], yi1 = sm.by1[i];
        float xi2 = sm.bx2[i], yi2 = sm.by2[i], ai = sm.ar[i];
        #pragma unroll
        for (int h = 0; h < 2; ++h) {
            int j = tid + h * 256;
            if (j > i) {
                float ix1 = fmaxf(xi1, sm.bx1[j]);
                float iy1 = fmaxf(yi1, sm.by1[j]);
                float ix2 = fminf(xi2, sm.bx2[j]);
                float iy2 = fminf(yi2, sm.by2[j]);
                float iw  = fmaxf(ix2 - ix1, 0.f);
                float ih  = fmaxf(iy2 - iy1, 0.f);
                float inter = iw * ih;
                float iou = inter / (ai + sm.ar[j] - inter);
                if (iou > NMS_TH) supp[j] = 1u;
            }
        }
        __syncthreads();
    }

    for (int s = tid; s < 512; s += 256) {
        unsigned node = 0xFFFFFFFFu - (unsigned)(sm.keys[s] & 0xFFFFFFFFull);
        g_mask[(long long)node * N_CLS + cls] = sm.supp[s] ? 0.f : 1.f;
    }
}

// ---------------------------------------------------------------------------
// Fill block: zero h_edge_emb via float4 stores
// ---------------------------------------------------------------------------
__device__ void fill_block(int fb, float* __restrict__ out)
{
    const int tid = threadIdx.x;
    float4* z = reinterpret_cast<float4*>(out + OFF_HEE);
    const long long n4 = (long long)E_EDGES * D_DIM / 4;
    const float4 zero = make_float4(0.f, 0.f, 0.f, 0.f);
    for (long long i = (long long)fb * 256 + tid; i < n4;
         i += (long long)FILL_BLOCKS * 256)
        z[i] = zero;
}

// ---------------------------------------------------------------------------
// K2: fused grid — [0,150) NMS | [150,541) HMMA GEMM | [541,701) fill
// ---------------------------------------------------------------------------
__global__ __launch_bounds__(256) void k2_main(
    const float* __restrict__ edge_emb,
    const float* __restrict__ boxes,
    float* __restrict__ out)
{
    __shared__ K2Smem sm;
    const int b = blockIdx.x;
    if (b < NMS_BLOCKS) {
        nms_block(sm.nms, b + 1, boxes);
    } else if (b < NMS_BLOCKS + GEMM_BLOCKS) {
        gemm_block(sm.g, b - NMS_BLOCKS, edge_emb, out + OFF_REC);
    } else {
        fill_block(b - NMS_BLOCKS - GEMM_BLOCKS, out);
    }
}

// ---------------------------------------------------------------------------
// K3: h_node_emb = (att * mask) @ nodes_schema.T
// ---------------------------------------------------------------------------
__global__ __launch_bounds__(256) void k3_hnode(float* __restrict__ out)
{
    __shared__ float am[4][N_CLS];
    const int n0 = blockIdx.x * 4;
    const int tid = threadIdx.x;

    for (int t = tid; t < 4 * N_CLS; t += 256) {
        int n = t / N_CLS, c = t - n * N_CLS;
        long long gi = (long long)(n0 + n) * N_CLS + c;
        am[n][c] = g_att[gi] * g_mask[gi];
    }
    __syncthreads();

    float acc[4][4] = {};
    #pragma unroll 4
    for (int c = 0; c < N_CLS; ++c) {
        float s0 = g_schT[c * D_DIM + tid];
        float s1 = g_schT[c * D_DIM + tid + 256];
        float s2 = g_schT[c * D_DIM + tid + 512];
        float s3 = g_schT[c * D_DIM + tid + 768];
        #pragma unroll
        for (int n = 0; n < 4; ++n) {
            float a = am[n][c];
            acc[n][0] += a * s0; acc[n][1] += a * s1;
            acc[n][2] += a * s2; acc[n][3] += a * s3;
        }
    }
    #pragma unroll
    for (int n = 0; n < 4; ++n)
        #pragma unroll
        for (int i = 0; i < 4; ++i)
            out[OFF_HNE + (long long)(n0 + n) * D_DIM + tid + i * 256] = acc[n][i];
}

// ---------------------------------------------------------------------------
// Entry point — inputs identified by element count
// ---------------------------------------------------------------------------
extern "C" void kernel_launch(void* const* d_in, const int* in_sizes, int n_in,
                              void* d_out, int out_size)
{
    const float *node_emb = nullptr, *edge_emb = nullptr, *boxes = nullptr,
                *nsch = nullptr, *esch = nullptr;
    for (int i = 0; i < n_in; ++i) {
        switch (in_sizes[i]) {
            case 524288:   node_emb = (const float*)d_in[i]; break;
            case 51200000: edge_emb = (const float*)d_in[i]; break;
            case 309248:   boxes    = (const float*)d_in[i]; break;
            case 154624:   nsch     = (const float*)d_in[i]; break;
            case 52224:    esch     = (const float*)d_in[i]; break;
            default: break;
        }
    }
    float* out = (float*)d_out;

    k0_prep<<<N_CLS + 64, 256>>>(nsch, esch);
    k1_node<<<128, 256>>>(node_emb, out);
    k2_main<<<NMS_BLOCKS + GEMM_BLOCKS + FILL_BLOCKS, 256>>>(edge_emb, boxes, out);
    k3_hnode<<<128, 256>>>(out);
}